// round 13
// baseline (speedup 1.0000x reference)
#include <cuda_runtime.h>
#include <cuda_bf16.h>
#include <cstdint>
#include <math.h>

using bf16 = __nv_bfloat16;

// tcgen05 only exists on the "a" variants; guard so non-a gencode passes compile.
#if defined(__CUDA_ARCH_FEAT_SM103_ALL) || defined(__CUDA_ARCH_FEAT_SM100_ALL) || \
    defined(__CUDA_ARCH_FEAT_SM101_ALL)
#define HAS_TCGEN05 1
#else
#define HAS_TCGEN05 0
#endif

// Problem constants
constexpr int N_   = 128;            // frames
constexpr int P_   = 256;            // points
constexpr int D_   = 256;            // input dim
constexpr int H_   = 16;             // heads
constexpr int M_   = 32;             // head dim
constexpr int OUT_ = H_ * M_;        // 512
constexpr int HID_ = 2048;
constexpr int NP_  = N_ * P_;        // 32768

// ---------------- scratch (device globals; no allocation allowed) ----------
__device__ float g_qkvt[(size_t)3 * H_ * P_ * M_ * N_];   // [w][h][j][m][i]  fp32
__device__ float g_qkv2[(size_t)3 * H_ * N_ * M_ * P_];   // [w][h][i][m][j]  fp32

__device__ __align__(16) bf16 g_xb_h[(size_t)NP_ * D_],    g_xb_l[(size_t)NP_ * D_];
__device__ __align__(16) bf16 g_wT_h[(size_t)3 * OUT_ * D_],   g_wT_l[(size_t)3 * OUT_ * D_];
__device__ __align__(16) bf16 g_wP_h[(size_t)3 * OUT_ * OUT_], g_wP_l[(size_t)3 * OUT_ * OUT_];
__device__ __align__(16) bf16 g_w1_h[(size_t)HID_ * OUT_], g_w1_l[(size_t)HID_ * OUT_];
__device__ __align__(16) bf16 g_w2_h[(size_t)OUT_ * HID_], g_w2_l[(size_t)OUT_ * HID_];
__device__ __align__(16) bf16 g_tt_h[(size_t)NP_ * OUT_],  g_tt_l[(size_t)NP_ * OUT_];
__device__ __align__(16) bf16 g_pa_h[(size_t)NP_ * OUT_],  g_pa_l[(size_t)NP_ * OUT_];
__device__ __align__(16) bf16 g_hd_h[(size_t)NP_ * HID_],  g_hd_l[(size_t)NP_ * HID_];

// single shared name for ALL kernels using dynamic smem
extern __shared__ char dyn_smem[];

// ---------------- PTX helpers (only instantiated when called) ---------------
__device__ __forceinline__ uint32_t smem_u32(const void* p) {
    uint32_t a;
    asm("{ .reg .u64 t; cvta.to.shared.u64 t, %1; cvt.u32.u64 %0, t; }" : "=r"(a) : "l"(p));
    return a;
}
__device__ __forceinline__ uint64_t make_desc_sw128(uint32_t addr) {
    // SW128, Blackwell version=1, SBO=64, LBO=1 (K-major, 128B rows)
    return (uint64_t(2) << 61) | (uint64_t(1) << 46) | (uint64_t(64) << 32) |
           (uint64_t(1) << 16) | ((uint64_t)(addr >> 4) & 0x3FFF);
}
#if HAS_TCGEN05
__device__ __forceinline__ void mma_f16_ss(uint32_t d, uint64_t ad, uint64_t bd,
                                           uint32_t idesc, uint32_t en) {
    asm volatile(
        "{\n\t.reg .pred p;\n\tsetp.ne.u32 p, %4, 0;\n\t"
        "tcgen05.mma.cta_group::1.kind::f16 [%0], %1, %2, %3, {%5,%5,%5,%5}, p;\n\t}"
        :: "r"(d), "l"(ad), "l"(bd), "r"(idesc), "r"(en), "r"(0u) : "memory");
}
__device__ __forceinline__ void mbar_init(uint32_t a, uint32_t cnt) {
    asm volatile("mbarrier.init.shared.b64 [%0], %1;" :: "r"(a), "r"(cnt) : "memory");
}
__device__ __forceinline__ void mbar_wait(uint32_t a, uint32_t parity) {
    asm volatile(
        "{\n\t.reg .pred P1;\n\t"
        "WL%=:\n\t"
        "mbarrier.try_wait.parity.acquire.cta.shared::cta.b64 P1, [%0], %1, 0x989680;\n\t"
        "@P1 bra.uni WD%=;\n\t"
        "bra.uni WL%=;\n\t"
        "WD%=:\n\t}"
        :: "r"(a), "r"(parity) : "memory");
}
__device__ __forceinline__ void tc_commit(uint32_t mbar) {
    asm volatile(
        "tcgen05.commit.cta_group::1.mbarrier::arrive::one.shared::cluster.b64 [%0];"
        :: "r"(mbar) : "memory");
}
__device__ __forceinline__ void tc_alloc(uint32_t dst, uint32_t ncols) {
    asm volatile("tcgen05.alloc.cta_group::1.sync.aligned.shared::cta.b32 [%0], %1;"
                 :: "r"(dst), "r"(ncols) : "memory");
}
__device__ __forceinline__ void tc_relinquish() {
    asm volatile("tcgen05.relinquish_alloc_permit.cta_group::1.sync.aligned;");
}
__device__ __forceinline__ void tc_dealloc(uint32_t tmem, uint32_t ncols) {
    asm volatile("tcgen05.dealloc.cta_group::1.sync.aligned.b32 %0, %1;" :: "r"(tmem), "r"(ncols));
}
__device__ __forceinline__ void tc_fence_after() {
    asm volatile("tcgen05.fence::after_thread_sync;" ::: "memory");
}
__device__ __forceinline__ void tc_wait_ld() {
    asm volatile("tcgen05.wait::ld.sync.aligned;" ::: "memory");
}
#define TC_LD_X32(r, addr) \
    asm volatile( \
        "tcgen05.ld.sync.aligned.32x32b.x32.b32 " \
        "{%0, %1, %2, %3, %4, %5, %6, %7, " \
        " %8, %9, %10, %11, %12, %13, %14, %15, " \
        " %16, %17, %18, %19, %20, %21, %22, %23, " \
        " %24, %25, %26, %27, %28, %29, %30, %31}, [%32];" \
        : "=r"((r)[0]),  "=r"((r)[1]),  "=r"((r)[2]),  "=r"((r)[3]), \
          "=r"((r)[4]),  "=r"((r)[5]),  "=r"((r)[6]),  "=r"((r)[7]), \
          "=r"((r)[8]),  "=r"((r)[9]),  "=r"((r)[10]), "=r"((r)[11]), \
          "=r"((r)[12]), "=r"((r)[13]), "=r"((r)[14]), "=r"((r)[15]), \
          "=r"((r)[16]), "=r"((r)[17]), "=r"((r)[18]), "=r"((r)[19]), \
          "=r"((r)[20]), "=r"((r)[21]), "=r"((r)[22]), "=r"((r)[23]), \
          "=r"((r)[24]), "=r"((r)[25]), "=r"((r)[26]), "=r"((r)[27]), \
          "=r"((r)[28]), "=r"((r)[29]), "=r"((r)[30]), "=r"((r)[31]) \
        : "r"(addr))
#endif  // HAS_TCGEN05

// ---------------------------------------------------------------------------
// Epilogue write (shared between tensor path and fallback)
// MODE 0: outF[r*Nglob+c] = v + bias[c]
// MODE 1: scatter stage A -> g_qkvt [w][h][j][m][i]
// MODE 2: scatter stage C -> g_qkv2 [w][h][i][m][j]
// MODE 3: v += bias; split to (oHi,oLo) [r*Nglob+c]
// ---------------------------------------------------------------------------
template <int MODE>
__device__ __forceinline__ void write_out(
    int w, int r, int cg, float v, int Nglob,
    float* __restrict__ outF, bf16* __restrict__ oHi, bf16* __restrict__ oLo,
    const float* __restrict__ bias)
{
    if (MODE == 0) {
        outF[(size_t)r * Nglob + cg] = v + bias[cg];
    } else if (MODE == 1) {
        const int fi = r / P_, pj = r % P_;
        const int hh = cg >> 5, mm = cg & 31;
        outF[(size_t)w * ((size_t)H_ * P_ * M_ * N_) +
             ((size_t)(hh * P_ + pj) * M_ + mm) * N_ + fi] = v;
    } else if (MODE == 2) {
        const int fi = r / P_, pj = r % P_;
        const int hh = cg >> 5, mm = cg & 31;
        outF[(size_t)w * ((size_t)H_ * N_ * M_ * P_) +
             ((size_t)(hh * N_ + fi) * M_ + mm) * P_ + pj] = v;
    } else {
        const float t = v + bias[cg];
        const bf16 hi = __float2bfloat16(t);
        oHi[(size_t)r * Nglob + cg] = hi;
        oLo[(size_t)r * Nglob + cg] = __float2bfloat16(t - __bfloat162float(hi));
    }
}

// ---------------------------------------------------------------------------
// Split-bf16 GEMM: C[m][n] = sum_k A[m][k]*B[n][k], tile 128x128, BK=64.
// Tensor path: tcgen05 kind::f16, 3 passes (hh, hl, lh) into fp32 TMEM acc.
// cp.async loads with 1-chunk software prefetch (wait_group 1), 3-buffer ring.
// Fallback path (non-a gencode passes only): naive SIMT, never runs on GB300.
// ---------------------------------------------------------------------------
constexpr int GBK  = 64;                         // K per chunk
constexpr int SUBT = 128 * GBK * 2;              // 16384 B per subtile
constexpr int BUFB = 4 * SUBT;                   // 65536 B per buffer
constexpr int NBUF = 3;
constexpr int GEMM_SMEM = NBUF * BUFB + 64;      // + ctrl

template <int MODE>
__global__ __launch_bounds__(128) void gemm_k(
    const bf16* __restrict__ Ahi, const bf16* __restrict__ Alo,
    const bf16* __restrict__ Bhi, const bf16* __restrict__ Blo,
    int Ktot, int Nglob, long bBatch,
    float* __restrict__ outF, bf16* __restrict__ oHi, bf16* __restrict__ oLo,
    const float* __restrict__ bias)
{
    const int tid = threadIdx.x, wid = tid >> 5, lane = tid & 31;
    const int n0 = blockIdx.x * 128, m0 = blockIdx.y * 128, w = blockIdx.z;

    const bf16* bh = Bhi + (size_t)w * bBatch;
    const bf16* bl = Blo + (size_t)w * bBatch;

#if HAS_TCGEN05
    const uint32_t sbase = smem_u32(dyn_smem);
    const uint32_t ctrl  = sbase + NBUF * BUFB;  // tmem ptr (4B)
    // mbarriers at ctrl+8, ctrl+16, ctrl+24

    const bf16* src = (wid == 0) ? Ahi : (wid == 1) ? Alo : (wid == 2) ? bh : bl;
    const int rbase = (wid < 2) ? m0 : n0;

    if (wid == 0) { tc_alloc(ctrl, 128); tc_relinquish(); }
    if (tid == 0) {
        mbar_init(ctrl + 8, 1);
        mbar_init(ctrl + 16, 1);
        mbar_init(ctrl + 24, 1);
    }
    __syncthreads();
    uint32_t tmem;
    asm volatile("ld.shared.b32 %0, [%1];" : "=r"(tmem) : "r"(ctrl));

    const int nc = Ktot / GBK;
    int wcnt[NBUF] = {0, 0, 0};
    const uint32_t idesc = 0x8200490u;  // f32 acc, bf16 a/b, N=128, M=128
    uint32_t first = 0;                  // enable_d flag (0 = overwrite on first)

    // per-thread fixed part of the load addressing
    const int rsub = lane >> 3;          // 0..3 row-within-group
    const int c16  = lane & 7;           // 16B column within 128B row

    // load one 128x64 subtile per warp into buffer `buf` for chunk `cix`
    auto load_chunk = [&](int cix) {
        const int buf = cix % NBUF;
        const uint32_t sub = sbase + buf * BUFB + wid * SUBT;
        const int k0 = cix * GBK;
        const bf16* gbase = src + (size_t)rsub * Ktot + k0 + c16 * 8;
#pragma unroll
        for (int it = 0; it < 32; it++) {
            const int row = it * 4 + rsub;
            const bf16* gsrc = gbase + (size_t)(rbase + it * 4) * Ktot;
            uint32_t off = row * 128 + c16 * 16;
            uint32_t sw = off ^ ((off >> 3) & 0x70);
            asm volatile("cp.async.cg.shared.global [%0], [%1], 16;"
                         :: "r"(sub + sw), "l"(gsrc) : "memory");
        }
        asm volatile("cp.async.commit_group;" ::: "memory");
    };

    // prologue: chunk 0 in flight
    load_chunk(0);

    for (int c = 0; c < nc; c++) {
        const int buf = c % NBUF;
        if (c + 1 < nc) {
            const int nb = (c + 1) % NBUF;
            if (c + 1 >= NBUF) {          // buffer reuse gated on MMA(c+1-NBUF)
                mbar_wait(ctrl + 8 + 8 * nb, wcnt[nb] & 1);
                wcnt[nb]++;
            }
            load_chunk(c + 1);            // prefetch next chunk
            asm volatile("cp.async.wait_group 1;" ::: "memory");  // chunk c done
        } else {
            asm volatile("cp.async.wait_group 0;" ::: "memory");
        }
        __syncthreads();
        if (tid == 0) {
            asm volatile("fence.proxy.async.shared::cta;" ::: "memory");
            const uint32_t bb = sbase + buf * BUFB;
            const uint64_t dAh = make_desc_sw128(bb);
            const uint64_t dAl = make_desc_sw128(bb + SUBT);
            const uint64_t dBh = make_desc_sw128(bb + 2 * SUBT);
            const uint64_t dBl = make_desc_sw128(bb + 3 * SUBT);
#pragma unroll
            for (int ks = 0; ks < 4; ks++) {
                mma_f16_ss(tmem, dAh + ks * 2, dBh + ks * 2, idesc, first); first = 1u;
                mma_f16_ss(tmem, dAh + ks * 2, dBl + ks * 2, idesc, 1u);
                mma_f16_ss(tmem, dAl + ks * 2, dBh + ks * 2, idesc, 1u);
            }
            tc_commit(ctrl + 8 + 8 * buf);
        }
    }
    // wait for the last chunk's commit (queue is in-order => all done)
    {
        const int lb = (nc - 1) % NBUF;
        mbar_wait(ctrl + 8 + 8 * lb, wcnt[lb] & 1);
    }
    tc_fence_after();

    // epilogue: each warp reads its 32-lane subpartition
    const int r = m0 + wid * 32 + lane;
#pragma unroll
    for (int cb = 0; cb < 128; cb += 32) {
        uint32_t d[32];
        TC_LD_X32(d, tmem + cb);
        tc_wait_ld();
#pragma unroll
        for (int cc = 0; cc < 32; cc++) {
            write_out<MODE>(w, r, n0 + cb + cc, __uint_as_float(d[cc]),
                            Nglob, outF, oHi, oLo, bias);
        }
    }
    __syncthreads();
    if (wid == 0) tc_dealloc(tmem, 128);

#else  // ---------- SIMT fallback (compiled for non-'a' targets only) -------
    const int r = m0 + tid;
    for (int cg0 = 0; cg0 < 128; cg0++) {
        const int cg = n0 + cg0;
        float acc = 0.f;
        for (int k = 0; k < Ktot; k++) {
            const float a = __bfloat162float(Ahi[(size_t)r * Ktot + k]) +
                            __bfloat162float(Alo[(size_t)r * Ktot + k]);
            const float b = __bfloat162float(bh[(size_t)cg * Ktot + k]) +
                            __bfloat162float(bl[(size_t)cg * Ktot + k]);
            acc += a * b;
        }
        write_out<MODE>(w, r, cg, acc, Nglob, outF, oHi, oLo, bias);
    }
#endif
}

// ---------------------------------------------------------------------------
// conversion kernels
// ---------------------------------------------------------------------------
__global__ void split_flat_k(const float* __restrict__ in, bf16* __restrict__ hi,
                             bf16* __restrict__ lo, int n)
{
    const int i = blockIdx.x * 256 + threadIdx.x;
    if (i < n) {
        const float v = in[i];
        const bf16 h = __float2bfloat16(v);
        hi[i] = h;
        lo[i] = __float2bfloat16(v - __bfloat162float(h));
    }
}

// in[z][k][n] -> out[z][n][k] with bf16 split
__global__ void packT_k(const float* __restrict__ in, bf16* __restrict__ hi,
                        bf16* __restrict__ lo, int K, int Nn)
{
    const int idx = blockIdx.x * 256 + threadIdx.x;
    const int total = K * Nn;
    if (idx >= total) return;
    const int n = idx / K, k = idx % K;
    const size_t zb = (size_t)blockIdx.y * total;
    const float v = in[zb + (size_t)k * Nn + n];
    const bf16 h = __float2bfloat16(v);
    hi[zb + idx] = h;
    lo[zb + idx] = __float2bfloat16(v - __bfloat162float(h));
}

// ---------------------------------------------------------------------------
// Stage B: temporal attention (fp32). One block per (h, j). 256 threads.
// Writes Tt[np][hm] as bf16 hi/lo.
// ---------------------------------------------------------------------------
__global__ __launch_bounds__(256) void temporal_attn_k(
    const float* __restrict__ qkvt, bf16* __restrict__ tt_h, bf16* __restrict__ tt_l)
{
    float* smem = (float*)dyn_smem;
    float* sQ = smem;               // M_*N_ = 4096
    float* sK = sQ + M_ * N_;
    float* sV = sK + M_ * N_;
    float* sS = sV + M_ * N_;       // N_*N_ = 16384

    const int h = blockIdx.x >> 8;
    const int j = blockIdx.x & 255;
    const int tid = threadIdx.x;
    const size_t wstride = (size_t)H_ * P_ * M_ * N_;
    const float* base = qkvt + ((size_t)h * P_ + j) * (M_ * N_);

    for (int t = tid; t < (M_ * N_) / 4; t += 256) {
        ((float4*)sQ)[t] = ((const float4*)base)[t];
        ((float4*)sK)[t] = ((const float4*)(base + wstride))[t];
        ((float4*)sV)[t] = ((const float4*)(base + 2 * wstride))[t];
    }
    __syncthreads();

    {
        const int tr = (tid >> 4) * 8, tc = (tid & 15) * 8;
        float acc[8][8];
#pragma unroll
        for (int i = 0; i < 8; i++)
#pragma unroll
            for (int jj = 0; jj < 8; jj++) acc[i][jj] = 0.f;
#pragma unroll 4
        for (int m = 0; m < M_; m++) {
            float a[8], b[8];
#pragma unroll
            for (int i = 0; i < 8; i++) a[i] = sQ[m * N_ + tr + i];
#pragma unroll
            for (int jj = 0; jj < 8; jj++) b[jj] = sK[m * N_ + tc + jj];
#pragma unroll
            for (int i = 0; i < 8; i++)
#pragma unroll
                for (int jj = 0; jj < 8; jj++) acc[i][jj] += a[i] * b[jj];
        }
#pragma unroll
        for (int i = 0; i < 8; i++)
#pragma unroll
            for (int jj = 0; jj < 8; jj++)
                sS[(tr + i) * N_ + tc + jj] = acc[i][jj];
    }
    __syncthreads();

    if (tid < N_) {
        const int r = tid;
        float s = 0.f;
        for (int it = 0; it < N_; it++) {
            const int c = (r + it) & (N_ - 1);
            const float e = __expf(sS[r * N_ + c]);
            sS[r * N_ + c] = e;
            s += e;
        }
        const float inv = 1.f / s;
        for (int it = 0; it < N_; it++) {
            const int c = (r + it) & (N_ - 1);
            sS[r * N_ + c] *= inv;
        }
    }
    __syncthreads();

    {
        const int mB = (tid >> 5) * 4;
        const int iB = (tid & 31) * 4;
        float o[4][4];
#pragma unroll
        for (int a = 0; a < 4; a++)
#pragma unroll
            for (int b = 0; b < 4; b++) o[a][b] = 0.f;
        for (int I = 0; I < N_; I++) {
            const float4 e = *(const float4*)&sS[I * N_ + iB];
#pragma unroll
            for (int a = 0; a < 4; a++) {
                const float v = sV[(mB + a) * N_ + I];
                o[a][0] += v * e.x;
                o[a][1] += v * e.y;
                o[a][2] += v * e.z;
                o[a][3] += v * e.w;
            }
        }
#pragma unroll
        for (int a = 0; a < 4; a++)
#pragma unroll
            for (int b = 0; b < 4; b++) {
                const int np = (iB + b) * P_ + j;
                const int hm = h * M_ + mB + a;
                const float t = o[a][b];
                const bf16 hi = __float2bfloat16(t);
                tt_h[(size_t)np * OUT_ + hm] = hi;
                tt_l[(size_t)np * OUT_ + hm] = __float2bfloat16(t - __bfloat162float(hi));
            }
    }
}

// ---------------------------------------------------------------------------
// Stage D: point attention (fp32). One block per (h, i), 256 threads (= query j).
// Writes pa[np][hm] as bf16 hi/lo.
// ---------------------------------------------------------------------------
__global__ __launch_bounds__(256) void point_attn_k(
    const float* __restrict__ qkv2, bf16* __restrict__ pa_h, bf16* __restrict__ pa_l)
{
    __shared__ float sK[M_ * P_];
    __shared__ float sV[M_ * P_];

    const int h = blockIdx.x >> 7;
    const int i = blockIdx.x & 127;
    const int tid = threadIdx.x;
    const size_t wstride = (size_t)H_ * N_ * M_ * P_;
    const float* base = qkv2 + ((size_t)h * N_ + i) * (M_ * P_);

    for (int t = tid; t < (M_ * P_) / 4; t += 256) {
        ((float4*)sK)[t] = ((const float4*)(base + wstride))[t];
        ((float4*)sV)[t] = ((const float4*)(base + 2 * wstride))[t];
    }
    float q[M_];
#pragma unroll
    for (int m = 0; m < M_; m++) q[m] = base[m * P_ + tid];
    __syncthreads();

    float o[M_];
#pragma unroll
    for (int m = 0; m < M_; m++) o[m] = 0.f;
    float ssum = 0.f;
    for (int J = 0; J < P_; J++) {
        float s = 0.f;
#pragma unroll
        for (int m = 0; m < M_; m++) s += q[m] * sK[m * P_ + J];
        const float e = __expf(s);
        ssum += e;
#pragma unroll
        for (int m = 0; m < M_; m++) o[m] += e * sV[m * P_ + J];
    }
    const float inv = 1.f / ssum;
    const size_t ob = ((size_t)i * P_ + tid) * OUT_ + h * M_;
#pragma unroll
    for (int m = 0; m < M_; m++) {
        const float t = o[m] * inv;
        const bf16 hi = __float2bfloat16(t);
        pa_h[ob + m] = hi;
        pa_l[ob + m] = __float2bfloat16(t - __bfloat162float(hi));
    }
}

// ---------------------------------------------------------------------------
extern "C" void kernel_launch(void* const* d_in, const int* in_sizes, int n_in,
                              void* d_out, int out_size)
{
    const float* x    = (const float*)d_in[0];  // (N,P,D)
    const float* qkvT = (const float*)d_in[1];  // (3,D,H,M)
    const float* qkvP = (const float*)d_in[2];  // (3,H,M,H,M)
    const float* W1   = (const float*)d_in[3];  // (512,2048)
    const float* b1   = (const float*)d_in[4];
    const float* W2   = (const float*)d_in[5];  // (2048,512)
    const float* b2   = (const float*)d_in[6];
    float* out = (float*)d_out;

    float *p_qkvt, *p_qkv2;
    bf16 *p_xb_h, *p_xb_l, *p_wT_h, *p_wT_l, *p_wP_h, *p_wP_l;
    bf16 *p_w1_h, *p_w1_l, *p_w2_h, *p_w2_l;
    bf16 *p_tt_h, *p_tt_l, *p_pa_h, *p_pa_l, *p_hd_h, *p_hd_l;
    cudaGetSymbolAddress((void**)&p_qkvt, g_qkvt);
    cudaGetSymbolAddress((void**)&p_qkv2, g_qkv2);
    cudaGetSymbolAddress((void**)&p_xb_h, g_xb_h);
    cudaGetSymbolAddress((void**)&p_xb_l, g_xb_l);
    cudaGetSymbolAddress((void**)&p_wT_h, g_wT_h);
    cudaGetSymbolAddress((void**)&p_wT_l, g_wT_l);
    cudaGetSymbolAddress((void**)&p_wP_h, g_wP_h);
    cudaGetSymbolAddress((void**)&p_wP_l, g_wP_l);
    cudaGetSymbolAddress((void**)&p_w1_h, g_w1_h);
    cudaGetSymbolAddress((void**)&p_w1_l, g_w1_l);
    cudaGetSymbolAddress((void**)&p_w2_h, g_w2_h);
    cudaGetSymbolAddress((void**)&p_w2_l, g_w2_l);
    cudaGetSymbolAddress((void**)&p_tt_h, g_tt_h);
    cudaGetSymbolAddress((void**)&p_tt_l, g_tt_l);
    cudaGetSymbolAddress((void**)&p_pa_h, g_pa_h);
    cudaGetSymbolAddress((void**)&p_pa_l, g_pa_l);
    cudaGetSymbolAddress((void**)&p_hd_h, g_hd_h);
    cudaGetSymbolAddress((void**)&p_hd_l, g_hd_l);

    cudaFuncSetAttribute(gemm_k<0>, cudaFuncAttributeMaxDynamicSharedMemorySize, GEMM_SMEM);
    cudaFuncSetAttribute(gemm_k<1>, cudaFuncAttributeMaxDynamicSharedMemorySize, GEMM_SMEM);
    cudaFuncSetAttribute(gemm_k<2>, cudaFuncAttributeMaxDynamicSharedMemorySize, GEMM_SMEM);
    cudaFuncSetAttribute(gemm_k<3>, cudaFuncAttributeMaxDynamicSharedMemorySize, GEMM_SMEM);

    // Launch order interleaves conversions with compute so the ncu capture slot
    // (-s 5 area) lands on a GEMM / attention kernel, not a trivial pack.
    // [0] split x
    split_flat_k<<<(NP_ * D_ + 255) / 256, 256>>>(x, p_xb_h, p_xb_l, NP_ * D_);
    // [1] pack qkvT (3,D=256,HM=512) -> [w][hm][d]
    {
        dim3 g((D_ * OUT_ + 255) / 256, 3);
        packT_k<<<g, 256>>>(qkvT, p_wT_h, p_wT_l, D_, OUT_);
    }
    // [2] Stage A: qkvt = X @ qkvT (per w), scatter fp32 -> g_qkvt
    {
        dim3 g(OUT_ / 128, NP_ / 128, 3);
        gemm_k<1><<<g, 128, GEMM_SMEM>>>(p_xb_h, p_xb_l, p_wT_h, p_wT_l,
                                         D_, OUT_, (long)OUT_ * D_,
                                         p_qkvt, nullptr, nullptr, nullptr);
    }
    // [3] Stage B: temporal attention
    {
        const int smem_bytes = (3 * M_ * N_ + N_ * N_) * (int)sizeof(float);
        cudaFuncSetAttribute(temporal_attn_k,
                             cudaFuncAttributeMaxDynamicSharedMemorySize, smem_bytes);
        temporal_attn_k<<<H_ * P_, 256, smem_bytes>>>(p_qkvt, p_tt_h, p_tt_l);
    }
    // [4] split qkvP
    split_flat_k<<<(3 * OUT_ * OUT_ + 255) / 256, 256>>>(qkvP, p_wP_h, p_wP_l,
                                                         3 * OUT_ * OUT_);
    // [5] Stage C: qkv2 = Tt @ qkvP^T (per w), scatter fp32 -> g_qkv2
    {
        dim3 g(OUT_ / 128, NP_ / 128, 3);
        gemm_k<2><<<g, 128, GEMM_SMEM>>>(p_tt_h, p_tt_l, p_wP_h, p_wP_l,
                                         OUT_, OUT_, (long)OUT_ * OUT_,
                                         p_qkv2, nullptr, nullptr, nullptr);
    }
    // [6] Stage D: point attention
    point_attn_k<<<H_ * N_, 256>>>(p_qkv2, p_pa_h, p_pa_l);

    // [7] pack W1 (512,2048) -> [hid][out]
    {
        dim3 g((OUT_ * HID_ + 255) / 256, 1);
        packT_k<<<g, 256>>>(W1, p_w1_h, p_w1_l, OUT_, HID_);
    }
    // [8] Stage E1
    {
        dim3 g1(HID_ / 128, NP_ / 128, 1);
        gemm_k<3><<<g1, 128, GEMM_SMEM>>>(p_pa_h, p_pa_l, p_w1_h, p_w1_l,
                                          OUT_, HID_, 0L,
                                          nullptr, p_hd_h, p_hd_l, b1);
    }
    // [9] pack W2 (2048,512) -> [out][hid]
    {
        dim3 g((HID_ * OUT_ + 255) / 256, 1);
        packT_k<<<g, 256>>>(W2, p_w2_h, p_w2_l, HID_, OUT_);
    }
    // [10] Stage E2
    {
        dim3 g2(OUT_ / 128, NP_ / 128, 1);
        gemm_k<0><<<g2, 128, GEMM_SMEM>>>(p_hd_h, p_hd_l, p_w2_h, p_w2_l,
                                          HID_, OUT_, 0L,
                                          out, nullptr, nullptr, b2);
    }
}

// round 15
// speedup vs baseline: 1.2891x; 1.2891x over previous
#include <cuda_runtime.h>
#include <cuda_bf16.h>
#include <cstdint>
#include <math.h>

using bf16 = __nv_bfloat16;

// tcgen05 only exists on the "a" variants; guard so non-a gencode passes compile.
#if defined(__CUDA_ARCH_FEAT_SM103_ALL) || defined(__CUDA_ARCH_FEAT_SM100_ALL) || \
    defined(__CUDA_ARCH_FEAT_SM101_ALL)
#define HAS_TCGEN05 1
#else
#define HAS_TCGEN05 0
#endif

// Problem constants
constexpr int N_   = 128;            // frames
constexpr int P_   = 256;            // points
constexpr int D_   = 256;            // input dim
constexpr int H_   = 16;             // heads
constexpr int M_   = 32;             // head dim
constexpr int OUT_ = H_ * M_;        // 512
constexpr int HID_ = 2048;
constexpr int NP_  = N_ * P_;        // 32768

// ---------------- scratch (device globals; no allocation allowed) ----------
__device__ float g_qkvt[(size_t)3 * H_ * P_ * M_ * N_];   // [w][h][j][m][i]  fp32

// stage-C outputs in attention-native fp32 layouts
__device__ __align__(16) float g_q2T[(size_t)H_ * N_ * P_ * M_];  // [h][i][j][m]
__device__ __align__(16) float g_k2T[(size_t)H_ * N_ * P_ * M_];  // [h][i][j][m]
__device__ __align__(16) float g_v2 [(size_t)H_ * N_ * M_ * P_];  // [h][i][m][j]

__device__ __align__(16) bf16 g_xb_h[(size_t)NP_ * D_],    g_xb_l[(size_t)NP_ * D_];
__device__ __align__(16) bf16 g_wT_h[(size_t)3 * OUT_ * D_],   g_wT_l[(size_t)3 * OUT_ * D_];
__device__ __align__(16) bf16 g_wP_h[(size_t)3 * OUT_ * OUT_], g_wP_l[(size_t)3 * OUT_ * OUT_];
__device__ __align__(16) bf16 g_w1_h[(size_t)HID_ * OUT_], g_w1_l[(size_t)HID_ * OUT_];
__device__ __align__(16) bf16 g_w2_h[(size_t)OUT_ * HID_], g_w2_l[(size_t)OUT_ * HID_];
__device__ __align__(16) bf16 g_tt_h[(size_t)NP_ * OUT_],  g_tt_l[(size_t)NP_ * OUT_];
__device__ __align__(16) bf16 g_pa_h[(size_t)NP_ * OUT_],  g_pa_l[(size_t)NP_ * OUT_];
__device__ __align__(16) bf16 g_hd_h[(size_t)NP_ * HID_],  g_hd_l[(size_t)NP_ * HID_];

// single shared name for ALL kernels using dynamic smem
extern __shared__ char dyn_smem[];

// ---------------- PTX helpers (only instantiated when called) ---------------
__device__ __forceinline__ uint32_t smem_u32(const void* p) {
    uint32_t a;
    asm("{ .reg .u64 t; cvta.to.shared.u64 t, %1; cvt.u32.u64 %0, t; }" : "=r"(a) : "l"(p));
    return a;
}
__device__ __forceinline__ uint64_t make_desc_sw128(uint32_t addr) {
    // SW128, Blackwell version=1, SBO=64, LBO=1 (K-major, 128B rows)
    return (uint64_t(2) << 61) | (uint64_t(1) << 46) | (uint64_t(64) << 32) |
           (uint64_t(1) << 16) | ((uint64_t)(addr >> 4) & 0x3FFF);
}
#if HAS_TCGEN05
__device__ __forceinline__ void mma_f16_ss(uint32_t d, uint64_t ad, uint64_t bd,
                                           uint32_t idesc, uint32_t en) {
    asm volatile(
        "{\n\t.reg .pred p;\n\tsetp.ne.u32 p, %4, 0;\n\t"
        "tcgen05.mma.cta_group::1.kind::f16 [%0], %1, %2, %3, {%5,%5,%5,%5}, p;\n\t}"
        :: "r"(d), "l"(ad), "l"(bd), "r"(idesc), "r"(en), "r"(0u) : "memory");
}
__device__ __forceinline__ void mma_tf32_ss(uint32_t d, uint64_t ad, uint64_t bd,
                                            uint32_t idesc, uint32_t en) {
    asm volatile(
        "{\n\t.reg .pred p;\n\tsetp.ne.u32 p, %4, 0;\n\t"
        "tcgen05.mma.cta_group::1.kind::tf32 [%0], %1, %2, %3, {%5,%5,%5,%5}, p;\n\t}"
        :: "r"(d), "l"(ad), "l"(bd), "r"(idesc), "r"(en), "r"(0u) : "memory");
}
__device__ __forceinline__ void mma_tf32_ts(uint32_t d, uint32_t at, uint64_t bd,
                                            uint32_t idesc, uint32_t en) {
    asm volatile(
        "{\n\t.reg .pred p;\n\tsetp.ne.u32 p, %4, 0;\n\t"
        "tcgen05.mma.cta_group::1.kind::tf32 [%0], [%1], %2, %3, {%5,%5,%5,%5}, p;\n\t}"
        :: "r"(d), "r"(at), "l"(bd), "r"(idesc), "r"(en), "r"(0u) : "memory");
}
__device__ __forceinline__ void mbar_init(uint32_t a, uint32_t cnt) {
    asm volatile("mbarrier.init.shared.b64 [%0], %1;" :: "r"(a), "r"(cnt) : "memory");
}
__device__ __forceinline__ void mbar_wait(uint32_t a, uint32_t parity) {
    asm volatile(
        "{\n\t.reg .pred P1;\n\t"
        "WL%=:\n\t"
        "mbarrier.try_wait.parity.acquire.cta.shared::cta.b64 P1, [%0], %1, 0x989680;\n\t"
        "@P1 bra.uni WD%=;\n\t"
        "bra.uni WL%=;\n\t"
        "WD%=:\n\t}"
        :: "r"(a), "r"(parity) : "memory");
}
__device__ __forceinline__ void tc_commit(uint32_t mbar) {
    asm volatile(
        "tcgen05.commit.cta_group::1.mbarrier::arrive::one.shared::cluster.b64 [%0];"
        :: "r"(mbar) : "memory");
}
__device__ __forceinline__ void tc_alloc(uint32_t dst, uint32_t ncols) {
    asm volatile("tcgen05.alloc.cta_group::1.sync.aligned.shared::cta.b32 [%0], %1;"
                 :: "r"(dst), "r"(ncols) : "memory");
}
__device__ __forceinline__ void tc_relinquish() {
    asm volatile("tcgen05.relinquish_alloc_permit.cta_group::1.sync.aligned;");
}
__device__ __forceinline__ void tc_dealloc(uint32_t tmem, uint32_t ncols) {
    asm volatile("tcgen05.dealloc.cta_group::1.sync.aligned.b32 %0, %1;" :: "r"(tmem), "r"(ncols));
}
__device__ __forceinline__ void tc_fence_after() {
    asm volatile("tcgen05.fence::after_thread_sync;" ::: "memory");
}
__device__ __forceinline__ void tc_fence_before() {
    asm volatile("tcgen05.fence::before_thread_sync;" ::: "memory");
}
__device__ __forceinline__ void tc_wait_ld() {
    asm volatile("tcgen05.wait::ld.sync.aligned;" ::: "memory");
}
__device__ __forceinline__ void tc_wait_st() {
    asm volatile("tcgen05.wait::st.sync.aligned;" ::: "memory");
}
#define TC_LD_X32(r, addr) \
    asm volatile( \
        "tcgen05.ld.sync.aligned.32x32b.x32.b32 " \
        "{%0, %1, %2, %3, %4, %5, %6, %7, " \
        " %8, %9, %10, %11, %12, %13, %14, %15, " \
        " %16, %17, %18, %19, %20, %21, %22, %23, " \
        " %24, %25, %26, %27, %28, %29, %30, %31}, [%32];" \
        : "=r"((r)[0]),  "=r"((r)[1]),  "=r"((r)[2]),  "=r"((r)[3]), \
          "=r"((r)[4]),  "=r"((r)[5]),  "=r"((r)[6]),  "=r"((r)[7]), \
          "=r"((r)[8]),  "=r"((r)[9]),  "=r"((r)[10]), "=r"((r)[11]), \
          "=r"((r)[12]), "=r"((r)[13]), "=r"((r)[14]), "=r"((r)[15]), \
          "=r"((r)[16]), "=r"((r)[17]), "=r"((r)[18]), "=r"((r)[19]), \
          "=r"((r)[20]), "=r"((r)[21]), "=r"((r)[22]), "=r"((r)[23]), \
          "=r"((r)[24]), "=r"((r)[25]), "=r"((r)[26]), "=r"((r)[27]), \
          "=r"((r)[28]), "=r"((r)[29]), "=r"((r)[30]), "=r"((r)[31]) \
        : "r"(addr))
#define TC_ST_X32(addr, r) \
    asm volatile( \
        "tcgen05.st.sync.aligned.32x32b.x32.b32 [%0], " \
        "{%1, %2, %3, %4, %5, %6, %7, %8, " \
        " %9, %10, %11, %12, %13, %14, %15, %16, " \
        " %17, %18, %19, %20, %21, %22, %23, %24, " \
        " %25, %26, %27, %28, %29, %30, %31, %32};" \
        :: "r"(addr), \
           "r"((r)[0]),  "r"((r)[1]),  "r"((r)[2]),  "r"((r)[3]), \
           "r"((r)[4]),  "r"((r)[5]),  "r"((r)[6]),  "r"((r)[7]), \
           "r"((r)[8]),  "r"((r)[9]),  "r"((r)[10]), "r"((r)[11]), \
           "r"((r)[12]), "r"((r)[13]), "r"((r)[14]), "r"((r)[15]), \
           "r"((r)[16]), "r"((r)[17]), "r"((r)[18]), "r"((r)[19]), \
           "r"((r)[20]), "r"((r)[21]), "r"((r)[22]), "r"((r)[23]), \
           "r"((r)[24]), "r"((r)[25]), "r"((r)[26]), "r"((r)[27]), \
           "r"((r)[28]), "r"((r)[29]), "r"((r)[30]), "r"((r)[31]) \
        : "memory")
#endif  // HAS_TCGEN05

// ---------------------------------------------------------------------------
// Epilogue write
// MODE 0: outF[r*Nglob+c] = v + bias[c]
// MODE 1: scatter stage A -> g_qkvt [w][h][j][m][i]
// MODE 2: scatter stage C -> g_q2T/g_k2T [h][i][j][m], g_v2 [h][i][m][j]
// MODE 3: v += bias; split to (oHi,oLo) [r*Nglob+c]
// ---------------------------------------------------------------------------
template <int MODE>
__device__ __forceinline__ void write_out(
    int w, int r, int cg, float v, int Nglob,
    float* __restrict__ outF, bf16* __restrict__ oHi, bf16* __restrict__ oLo,
    const float* __restrict__ bias)
{
    if (MODE == 0) {
        outF[(size_t)r * Nglob + cg] = v + bias[cg];
    } else if (MODE == 1) {
        const int fi = r / P_, pj = r % P_;
        const int hh = cg >> 5, mm = cg & 31;
        outF[(size_t)w * ((size_t)H_ * P_ * M_ * N_) +
             ((size_t)(hh * P_ + pj) * M_ + mm) * N_ + fi] = v;
    } else if (MODE == 2) {
        const int fi = r / P_, pj = r % P_;
        const int hh = cg >> 5, mm = cg & 31;
        if (w == 0)
            g_q2T[(((size_t)hh * N_ + fi) * P_ + pj) * M_ + mm] = v;
        else if (w == 1)
            g_k2T[(((size_t)hh * N_ + fi) * P_ + pj) * M_ + mm] = v;
        else
            g_v2[(((size_t)hh * N_ + fi) * M_ + mm) * P_ + pj] = v;
    } else {
        const float t = v + bias[cg];
        const bf16 hi = __float2bfloat16(t);
        oHi[(size_t)r * Nglob + cg] = hi;
        oLo[(size_t)r * Nglob + cg] = __float2bfloat16(t - __bfloat162float(hi));
    }
}

// ---------------------------------------------------------------------------
// Split-bf16 GEMM (unchanged from R13 winner)
// ---------------------------------------------------------------------------
constexpr int GBK  = 64;
constexpr int SUBT = 128 * GBK * 2;
constexpr int BUFB = 4 * SUBT;
constexpr int NBUF = 3;
constexpr int GEMM_SMEM = NBUF * BUFB + 64;

template <int MODE>
__global__ __launch_bounds__(128) void gemm_k(
    const bf16* __restrict__ Ahi, const bf16* __restrict__ Alo,
    const bf16* __restrict__ Bhi, const bf16* __restrict__ Blo,
    int Ktot, int Nglob, long bBatch,
    float* __restrict__ outF, bf16* __restrict__ oHi, bf16* __restrict__ oLo,
    const float* __restrict__ bias)
{
    const int tid = threadIdx.x, wid = tid >> 5, lane = tid & 31;
    const int n0 = blockIdx.x * 128, m0 = blockIdx.y * 128, w = blockIdx.z;

    const bf16* bh = Bhi + (size_t)w * bBatch;
    const bf16* bl = Blo + (size_t)w * bBatch;

#if HAS_TCGEN05
    const uint32_t sbase = smem_u32(dyn_smem);
    const uint32_t ctrl  = sbase + NBUF * BUFB;

    const bf16* src = (wid == 0) ? Ahi : (wid == 1) ? Alo : (wid == 2) ? bh : bl;
    const int rbase = (wid < 2) ? m0 : n0;

    if (wid == 0) { tc_alloc(ctrl, 128); tc_relinquish(); }
    if (tid == 0) {
        mbar_init(ctrl + 8, 1);
        mbar_init(ctrl + 16, 1);
        mbar_init(ctrl + 24, 1);
    }
    __syncthreads();
    uint32_t tmem;
    asm volatile("ld.shared.b32 %0, [%1];" : "=r"(tmem) : "r"(ctrl));

    const int nc = Ktot / GBK;
    int wcnt[NBUF] = {0, 0, 0};
    const uint32_t idesc = 0x8200490u;  // f32 acc, bf16 a/b, N=128, M=128
    uint32_t first = 0;

    const int rsub = lane >> 3;
    const int c16  = lane & 7;

    auto load_chunk = [&](int cix) {
        const int buf = cix % NBUF;
        const uint32_t sub = sbase + buf * BUFB + wid * SUBT;
        const int k0 = cix * GBK;
        const bf16* gbase = src + (size_t)rsub * Ktot + k0 + c16 * 8;
#pragma unroll
        for (int it = 0; it < 32; it++) {
            const int row = it * 4 + rsub;
            const bf16* gsrc = gbase + (size_t)(rbase + it * 4) * Ktot;
            uint32_t off = row * 128 + c16 * 16;
            uint32_t sw = off ^ ((off >> 3) & 0x70);
            asm volatile("cp.async.cg.shared.global [%0], [%1], 16;"
                         :: "r"(sub + sw), "l"(gsrc) : "memory");
        }
        asm volatile("cp.async.commit_group;" ::: "memory");
    };

    load_chunk(0);

    for (int c = 0; c < nc; c++) {
        const int buf = c % NBUF;
        if (c + 1 < nc) {
            const int nb = (c + 1) % NBUF;
            if (c + 1 >= NBUF) {
                mbar_wait(ctrl + 8 + 8 * nb, wcnt[nb] & 1);
                wcnt[nb]++;
            }
            load_chunk(c + 1);
            asm volatile("cp.async.wait_group 1;" ::: "memory");
        } else {
            asm volatile("cp.async.wait_group 0;" ::: "memory");
        }
        __syncthreads();
        if (tid == 0) {
            asm volatile("fence.proxy.async.shared::cta;" ::: "memory");
            const uint32_t bb = sbase + buf * BUFB;
            const uint64_t dAh = make_desc_sw128(bb);
            const uint64_t dAl = make_desc_sw128(bb + SUBT);
            const uint64_t dBh = make_desc_sw128(bb + 2 * SUBT);
            const uint64_t dBl = make_desc_sw128(bb + 3 * SUBT);
#pragma unroll
            for (int ks = 0; ks < 4; ks++) {
                mma_f16_ss(tmem, dAh + ks * 2, dBh + ks * 2, idesc, first); first = 1u;
                mma_f16_ss(tmem, dAh + ks * 2, dBl + ks * 2, idesc, 1u);
                mma_f16_ss(tmem, dAl + ks * 2, dBh + ks * 2, idesc, 1u);
            }
            tc_commit(ctrl + 8 + 8 * buf);
        }
    }
    {
        const int lb = (nc - 1) % NBUF;
        mbar_wait(ctrl + 8 + 8 * lb, wcnt[lb] & 1);
    }
    tc_fence_after();

    const int r = m0 + wid * 32 + lane;
#pragma unroll
    for (int cb = 0; cb < 128; cb += 32) {
        uint32_t d[32];
        TC_LD_X32(d, tmem + cb);
        tc_wait_ld();
#pragma unroll
        for (int cc = 0; cc < 32; cc++) {
            write_out<MODE>(w, r, n0 + cb + cc, __uint_as_float(d[cc]),
                            Nglob, outF, oHi, oLo, bias);
        }
    }
    __syncthreads();
    if (wid == 0) tc_dealloc(tmem, 128);

#else  // SIMT fallback (non-'a' targets only)
    const int r = m0 + tid;
    for (int cg0 = 0; cg0 < 128; cg0++) {
        const int cg = n0 + cg0;
        float acc = 0.f;
        for (int k = 0; k < Ktot; k++) {
            const float a = __bfloat162float(Ahi[(size_t)r * Ktot + k]) +
                            __bfloat162float(Alo[(size_t)r * Ktot + k]);
            const float b = __bfloat162float(bh[(size_t)cg * Ktot + k]) +
                            __bfloat162float(bl[(size_t)cg * Ktot + k]);
            acc += a * b;
        }
        write_out<MODE>(w, r, cg, acc, Nglob, outF, oHi, oLo, bias);
    }
#endif
}

// ---------------------------------------------------------------------------
// conversion kernels
// ---------------------------------------------------------------------------
__global__ void split_flat_k(const float* __restrict__ in, bf16* __restrict__ hi,
                             bf16* __restrict__ lo, int n)
{
    const int i = blockIdx.x * 256 + threadIdx.x;
    if (i < n) {
        const float v = in[i];
        const bf16 h = __float2bfloat16(v);
        hi[i] = h;
        lo[i] = __float2bfloat16(v - __bfloat162float(h));
    }
}

__global__ void packT_k(const float* __restrict__ in, bf16* __restrict__ hi,
                        bf16* __restrict__ lo, int K, int Nn)
{
    const int idx = blockIdx.x * 256 + threadIdx.x;
    const int total = K * Nn;
    if (idx >= total) return;
    const int n = idx / K, k = idx % K;
    const size_t zb = (size_t)blockIdx.y * total;
    const float v = in[zb + (size_t)k * Nn + n];
    const bf16 h = __float2bfloat16(v);
    hi[zb + idx] = h;
    lo[zb + idx] = __float2bfloat16(v - __bfloat162float(h));
}

// ---------------------------------------------------------------------------
// Stage B: temporal attention (fp32 SIMT, unchanged). One block per (h, j).
// ---------------------------------------------------------------------------
__global__ __launch_bounds__(256) void temporal_attn_k(
    const float* __restrict__ qkvt, bf16* __restrict__ tt_h, bf16* __restrict__ tt_l)
{
    float* smem = (float*)dyn_smem;
    float* sQ = smem;
    float* sK = sQ + M_ * N_;
    float* sV = sK + M_ * N_;
    float* sS = sV + M_ * N_;

    const int h = blockIdx.x >> 8;
    const int j = blockIdx.x & 255;
    const int tid = threadIdx.x;
    const size_t wstride = (size_t)H_ * P_ * M_ * N_;
    const float* base = qkvt + ((size_t)h * P_ + j) * (M_ * N_);

    for (int t = tid; t < (M_ * N_) / 4; t += 256) {
        ((float4*)sQ)[t] = ((const float4*)base)[t];
        ((float4*)sK)[t] = ((const float4*)(base + wstride))[t];
        ((float4*)sV)[t] = ((const float4*)(base + 2 * wstride))[t];
    }
    __syncthreads();

    {
        const int tr = (tid >> 4) * 8, tc = (tid & 15) * 8;
        float acc[8][8];
#pragma unroll
        for (int i = 0; i < 8; i++)
#pragma unroll
            for (int jj = 0; jj < 8; jj++) acc[i][jj] = 0.f;
#pragma unroll 4
        for (int m = 0; m < M_; m++) {
            float a[8], b[8];
#pragma unroll
            for (int i = 0; i < 8; i++) a[i] = sQ[m * N_ + tr + i];
#pragma unroll
            for (int jj = 0; jj < 8; jj++) b[jj] = sK[m * N_ + tc + jj];
#pragma unroll
            for (int i = 0; i < 8; i++)
#pragma unroll
                for (int jj = 0; jj < 8; jj++) acc[i][jj] += a[i] * b[jj];
        }
#pragma unroll
        for (int i = 0; i < 8; i++)
#pragma unroll
            for (int jj = 0; jj < 8; jj++)
                sS[(tr + i) * N_ + tc + jj] = acc[i][jj];
    }
    __syncthreads();

    if (tid < N_) {
        const int r = tid;
        float s = 0.f;
        for (int it = 0; it < N_; it++) {
            const int c = (r + it) & (N_ - 1);
            const float e = __expf(sS[r * N_ + c]);
            sS[r * N_ + c] = e;
            s += e;
        }
        const float inv = 1.f / s;
        for (int it = 0; it < N_; it++) {
            const int c = (r + it) & (N_ - 1);
            sS[r * N_ + c] *= inv;
        }
    }
    __syncthreads();

    {
        const int mB = (tid >> 5) * 4;
        const int iB = (tid & 31) * 4;
        float o[4][4];
#pragma unroll
        for (int a = 0; a < 4; a++)
#pragma unroll
            for (int b = 0; b < 4; b++) o[a][b] = 0.f;
        for (int I = 0; I < N_; I++) {
            const float4 e = *(const float4*)&sS[I * N_ + iB];
#pragma unroll
            for (int a = 0; a < 4; a++) {
                const float v = sV[(mB + a) * N_ + I];
                o[a][0] += v * e.x;
                o[a][1] += v * e.y;
                o[a][2] += v * e.z;
                o[a][3] += v * e.w;
            }
        }
#pragma unroll
        for (int a = 0; a < 4; a++)
#pragma unroll
            for (int b = 0; b < 4; b++) {
                const int np = (iB + b) * P_ + j;
                const int hm = h * M_ + mB + a;
                const float t = o[a][b];
                const bf16 hi = __float2bfloat16(t);
                tt_h[(size_t)np * OUT_ + hm] = hi;
                tt_l[(size_t)np * OUT_ + hm] = __float2bfloat16(t - __bfloat162float(hi));
            }
    }
}

// ---------------------------------------------------------------------------
// Stage D: point attention on tcgen05 (tf32). One block per (h, i), 128 thr.
//  S[j][J] = sum_m Q[m][j] K[m][J]   (MMA1, SS: A=Q^T half [128x32], B=K^T [256x32])
//  W = exp(S) in-place in TMEM (tf32-rounded; ssum accumulated from rounded vals)
//  O[j][m] = sum_J W[j][J] V[m][J]   (MMA2, TS: A=W in TMEM, B=V [32x256])
//  pa[np][hm] = O * (1/ssum), split bf16.
// ---------------------------------------------------------------------------
constexpr int PT_SMEM = 96 * 1024 + 64;

__global__ __launch_bounds__(128) void point_attn_tc_k()
{
    const int tid = threadIdx.x;
    const int h = blockIdx.x >> 7;
    const int i = blockIdx.x & 127;
#if HAS_TCGEN05
    const int wid = tid >> 5, lane = tid & 31;
    const uint32_t sbase = smem_u32(dyn_smem);
    const uint32_t sQ = sbase;              // 32KB: Q^T 256x32 f32, 128B rows SW128
    const uint32_t sK = sbase + 32 * 1024;  // 32KB: K^T 256x32 f32
    const uint32_t sV = sbase + 64 * 1024;  // 32KB: V 32x256 f32, blocked SW128 atoms
    const uint32_t ctrl = sbase + 96 * 1024;
    const uint32_t mb = ctrl + 8;

    const float* qb = g_q2T + ((size_t)h * N_ + i) * (P_ * M_);
    const float* kb = g_k2T + ((size_t)h * N_ + i) * (P_ * M_);
    const float* vb = g_v2  + ((size_t)h * N_ + i) * (M_ * P_);

    // Q^T/K^T: row j, 8 x 16B chunks per row
    for (int t = tid; t < 2048; t += 128) {
        const int j = t >> 3, c = t & 7;
        uint32_t off = j * 128 + c * 16;
        uint32_t sw = off ^ ((off >> 3) & 0x70);
        asm volatile("cp.async.cg.shared.global [%0], [%1], 16;"
                     :: "r"(sQ + sw), "l"(qb + (size_t)t * 4) : "memory");
        asm volatile("cp.async.cg.shared.global [%0], [%1], 16;"
                     :: "r"(sK + sw), "l"(kb + (size_t)t * 4) : "memory");
    }
    // V: row m (32), 64 x 16B chunks per row; blocked atoms: atom_off = m/8 + (J/32)*4
    for (int t = tid; t < 2048; t += 128) {
        const int m = t >> 6, c = t & 63;
        const int J0 = c * 4;
        uint32_t off = (m >> 3) * 1024 + (J0 >> 5) * 4096 + (m & 7) * 128 + (J0 & 31) * 4;
        uint32_t sw = off ^ ((off >> 3) & 0x70);
        asm volatile("cp.async.cg.shared.global [%0], [%1], 16;"
                     :: "r"(sV + sw), "l"(vb + (size_t)t * 4) : "memory");
    }
    asm volatile("cp.async.commit_group;" ::: "memory");

    if (wid == 0) { tc_alloc(ctrl, 512); tc_relinquish(); }
    if (tid == 0) mbar_init(mb, 1);
    asm volatile("cp.async.wait_group 0;" ::: "memory");
    __syncthreads();
    uint32_t tmem;
    asm volatile("ld.shared.b32 %0, [%1];" : "=r"(tmem) : "r"(ctrl));

    const uint32_t idesc1 = 0x8400910u;  // tf32, f32 acc, M=128, N=256
    const uint32_t idesc2 = 0x8080910u;  // tf32, f32 acc, M=128, N=32
    const uint32_t woff = (uint32_t)(tid >> 5) << 21;   // st subpartition select
    int phase = 0;

    for (int half = 0; half < 2; half++) {
        // ---- MMA1: S = Qhalf^T @ K  (K=32 -> 4 tf32 k-steps) ----
        if (tid == 0) {
            asm volatile("fence.proxy.async.shared::cta;" ::: "memory");
            const uint64_t da = make_desc_sw128(sQ + half * 16384);
            const uint64_t db = make_desc_sw128(sK);
#pragma unroll
            for (int ks = 0; ks < 4; ks++)
                mma_tf32_ss(tmem, da + ks * 2, db + ks * 2, idesc1, ks > 0);
            tc_commit(mb);
        }
        __syncthreads();
        mbar_wait(mb, phase); phase ^= 1;
        tc_fence_after();

        // ---- softmax in place: e = exp(S), rounded to tf32; ssum over rounded ----
        float ssum = 0.f;
#pragma unroll
        for (int cb = 0; cb < 256; cb += 32) {
            uint32_t d[32];
            TC_LD_X32(d, tmem + cb);
            tc_wait_ld();
#pragma unroll
            for (int c = 0; c < 32; c++) {
                const float e = __expf(__uint_as_float(d[c]));
                uint32_t et;
                asm("cvt.rna.tf32.f32 %0, %1;" : "=r"(et) : "f"(e));
                ssum += __uint_as_float(et);
                d[c] = et;
            }
            TC_ST_X32(tmem + cb + woff, d);
        }
        tc_wait_st();
        tc_fence_before();
        __syncthreads();

        // ---- MMA2: O = W @ V^T  (TS mode, K=256 -> 32 tf32 k-steps) ----
        if (tid == 0) {
            tc_fence_after();
            const uint64_t dv = make_desc_sw128(sV);
#pragma unroll
            for (int ks = 0; ks < 32; ks++) {
                const uint32_t atm = tmem + ks * 8;
                const uint64_t db = dv + (uint64_t)((ks >> 2) * 256 + (ks & 3) * 2);
                mma_tf32_ts(tmem + 256, atm, db, idesc2, ks > 0);
            }
            tc_commit(mb);
        }
        __syncthreads();
        mbar_wait(mb, phase); phase ^= 1;
        tc_fence_after();

        // ---- read O, normalize, split-bf16 store to pa ----
        {
            uint32_t d2[32];
            TC_LD_X32(d2, tmem + 256);
            tc_wait_ld();
            const float inv = 1.f / ssum;
            const int j = half * 128 + wid * 32 + lane;
            const size_t ob = ((size_t)i * P_ + j) * OUT_ + h * M_;
#pragma unroll
            for (int m = 0; m < 32; m++) {
                const float t = __uint_as_float(d2[m]) * inv;
                const bf16 hi = __float2bfloat16(t);
                g_pa_h[ob + m] = hi;
                g_pa_l[ob + m] = __float2bfloat16(t - __bfloat162float(hi));
            }
        }
        tc_fence_before();
        __syncthreads();
    }
    if (wid == 0) tc_dealloc(tmem, 512);

#else  // SIMT fallback (non-'a' targets only)
    const float* qb = g_q2T + ((size_t)h * N_ + i) * (P_ * M_);
    const float* kb = g_k2T + ((size_t)h * N_ + i) * (P_ * M_);
    const float* vb = g_v2  + ((size_t)h * N_ + i) * (M_ * P_);
    for (int j = tid; j < P_; j += blockDim.x) {
        float o[M_];
        for (int m = 0; m < M_; m++) o[m] = 0.f;
        float ssum = 0.f;
        for (int J = 0; J < P_; J++) {
            float s = 0.f;
            for (int m = 0; m < M_; m++)
                s += qb[(size_t)j * M_ + m] * kb[(size_t)J * M_ + m];
            const float e = __expf(s);
            ssum += e;
            for (int m = 0; m < M_; m++) o[m] += e * vb[(size_t)m * P_ + J];
        }
        const float inv = 1.f / ssum;
        const size_t ob = ((size_t)i * P_ + j) * OUT_ + h * M_;
        for (int m = 0; m < M_; m++) {
            const float t = o[m] * inv;
            const bf16 hi = __float2bfloat16(t);
            g_pa_h[ob + m] = hi;
            g_pa_l[ob + m] = __float2bfloat16(t - __bfloat162float(hi));
        }
    }
#endif
}

// ---------------------------------------------------------------------------
extern "C" void kernel_launch(void* const* d_in, const int* in_sizes, int n_in,
                              void* d_out, int out_size)
{
    const float* x    = (const float*)d_in[0];  // (N,P,D)
    const float* qkvT = (const float*)d_in[1];  // (3,D,H,M)
    const float* qkvP = (const float*)d_in[2];  // (3,H,M,H,M)
    const float* W1   = (const float*)d_in[3];  // (512,2048)
    const float* b1   = (const float*)d_in[4];
    const float* W2   = (const float*)d_in[5];  // (2048,512)
    const float* b2   = (const float*)d_in[6];
    float* out = (float*)d_out;

    float *p_qkvt;
    bf16 *p_xb_h, *p_xb_l, *p_wT_h, *p_wT_l, *p_wP_h, *p_wP_l;
    bf16 *p_w1_h, *p_w1_l, *p_w2_h, *p_w2_l;
    bf16 *p_tt_h, *p_tt_l, *p_pa_h, *p_pa_l, *p_hd_h, *p_hd_l;
    cudaGetSymbolAddress((void**)&p_qkvt, g_qkvt);
    cudaGetSymbolAddress((void**)&p_xb_h, g_xb_h);
    cudaGetSymbolAddress((void**)&p_xb_l, g_xb_l);
    cudaGetSymbolAddress((void**)&p_wT_h, g_wT_h);
    cudaGetSymbolAddress((void**)&p_wT_l, g_wT_l);
    cudaGetSymbolAddress((void**)&p_wP_h, g_wP_h);
    cudaGetSymbolAddress((void**)&p_wP_l, g_wP_l);
    cudaGetSymbolAddress((void**)&p_w1_h, g_w1_h);
    cudaGetSymbolAddress((void**)&p_w1_l, g_w1_l);
    cudaGetSymbolAddress((void**)&p_w2_h, g_w2_h);
    cudaGetSymbolAddress((void**)&p_w2_l, g_w2_l);
    cudaGetSymbolAddress((void**)&p_tt_h, g_tt_h);
    cudaGetSymbolAddress((void**)&p_tt_l, g_tt_l);
    cudaGetSymbolAddress((void**)&p_pa_h, g_pa_h);
    cudaGetSymbolAddress((void**)&p_pa_l, g_pa_l);
    cudaGetSymbolAddress((void**)&p_hd_h, g_hd_h);
    cudaGetSymbolAddress((void**)&p_hd_l, g_hd_l);

    cudaFuncSetAttribute(gemm_k<0>, cudaFuncAttributeMaxDynamicSharedMemorySize, GEMM_SMEM);
    cudaFuncSetAttribute(gemm_k<1>, cudaFuncAttributeMaxDynamicSharedMemorySize, GEMM_SMEM);
    cudaFuncSetAttribute(gemm_k<2>, cudaFuncAttributeMaxDynamicSharedMemorySize, GEMM_SMEM);
    cudaFuncSetAttribute(gemm_k<3>, cudaFuncAttributeMaxDynamicSharedMemorySize, GEMM_SMEM);
    cudaFuncSetAttribute(point_attn_tc_k, cudaFuncAttributeMaxDynamicSharedMemorySize, PT_SMEM);

    // [0] split x
    split_flat_k<<<(NP_ * D_ + 255) / 256, 256>>>(x, p_xb_h, p_xb_l, NP_ * D_);
    // [1] pack qkvT (3,D,HM) -> [w][hm][d]
    {
        dim3 g((D_ * OUT_ + 255) / 256, 3);
        packT_k<<<g, 256>>>(qkvT, p_wT_h, p_wT_l, D_, OUT_);
    }
    // [2] Stage A: qkvt = X @ qkvT (per w), scatter fp32 -> g_qkvt
    {
        dim3 g(OUT_ / 128, NP_ / 128, 3);
        gemm_k<1><<<g, 128, GEMM_SMEM>>>(p_xb_h, p_xb_l, p_wT_h, p_wT_l,
                                         D_, OUT_, (long)OUT_ * D_,
                                         p_qkvt, nullptr, nullptr, nullptr);
    }
    // [3] Stage B: temporal attention
    {
        const int smem_bytes = (3 * M_ * N_ + N_ * N_) * (int)sizeof(float);
        cudaFuncSetAttribute(temporal_attn_k,
                             cudaFuncAttributeMaxDynamicSharedMemorySize, smem_bytes);
        temporal_attn_k<<<H_ * P_, 256, smem_bytes>>>(p_qkvt, p_tt_h, p_tt_l);
    }
    // [4] split qkvP
    split_flat_k<<<(3 * OUT_ * OUT_ + 255) / 256, 256>>>(qkvP, p_wP_h, p_wP_l,
                                                         3 * OUT_ * OUT_);
    // [5] Stage C: scatter fp32 -> g_q2T / g_k2T / g_v2 (attention-native layouts)
    {
        dim3 g(OUT_ / 128, NP_ / 128, 3);
        gemm_k<2><<<g, 128, GEMM_SMEM>>>(p_tt_h, p_tt_l, p_wP_h, p_wP_l,
                                         OUT_, OUT_, (long)OUT_ * OUT_,
                                         nullptr, nullptr, nullptr, nullptr);
    }
    // [6] Stage D: point attention on tcgen05 (tf32)
    point_attn_tc_k<<<H_ * N_, 128, PT_SMEM>>>();

    // [7] pack W1 (512,2048) -> [hid][out]
    {
        dim3 g((OUT_ * HID_ + 255) / 256, 1);
        packT_k<<<g, 256>>>(W1, p_w1_h, p_w1_l, OUT_, HID_);
    }
    // [8] Stage E1
    {
        dim3 g1(HID_ / 128, NP_ / 128, 1);
        gemm_k<3><<<g1, 128, GEMM_SMEM>>>(p_pa_h, p_pa_l, p_w1_h, p_w1_l,
                                          OUT_, HID_, 0L,
                                          nullptr, p_hd_h, p_hd_l, b1);
    }
    // [9] pack W2 (2048,512) -> [out][hid]
    {
        dim3 g((HID_ * OUT_ + 255) / 256, 1);
        packT_k<<<g, 256>>>(W2, p_w2_h, p_w2_l, HID_, OUT_);
    }
    // [10] Stage E2
    {
        dim3 g2(OUT_ / 128, NP_ / 128, 1);
        gemm_k<0><<<g2, 128, GEMM_SMEM>>>(p_hd_h, p_hd_l, p_w2_h, p_w2_l,
                                          HID_, OUT_, 0L,
                                          out, nullptr, nullptr, b2);
    }
}